// round 2
// baseline (speedup 1.0000x reference)
#include <cuda_runtime.h>
#include <math.h>

#define B_  4
#define T_  2048
#define D_  1024
#define H_  16
#define HD_ 64
#define BT_ (B_ * T_)            // 8192
#define QKV_N (3 * D_)           // 3072

// Scratch (allocation-free rule: __device__ globals)
__device__ float g_qkv[(size_t)BT_ * QKV_N];   // [8192, 3072] : q | k | v
__device__ float g_att[(size_t)BT_ * D_];      // [8192, 1024] attention output (B,T,H*HD)

// ---------------------------------------------------------------------------
// SGEMM: C[M,N] = A[M,K] @ B[K,N], fp32. 128x128 tile, BK=8, 256 threads,
// 8x8 register microtile per thread. All dims are multiples of 128/8 here.
// ---------------------------------------------------------------------------
__global__ __launch_bounds__(256) void sgemm_kernel(
    const float* __restrict__ A, const float* __restrict__ Bm,
    float* __restrict__ C, int M, int N, int K)
{
    __shared__ float As[8][128];   // transposed: As[k][m]
    __shared__ float Bs[8][128];   // Bs[k][n]

    const int tid = threadIdx.x;
    const int bm  = blockIdx.y * 128;
    const int bn  = blockIdx.x * 128;
    const int tr  = tid >> 4;          // 0..15 -> rows tr*8..+7
    const int tc  = tid & 15;          // 0..15 -> cols tc*8..+7

    // global load mapping
    const int arow = tid >> 1;             // 0..127
    const int acol = (tid & 1) * 4;        // 0 or 4
    const int brow = tid >> 5;             // 0..7
    const int bcol = (tid & 31) * 4;       // 0..124

    float acc[8][8];
#pragma unroll
    for (int i = 0; i < 8; i++)
#pragma unroll
        for (int j = 0; j < 8; j++) acc[i][j] = 0.0f;

    const float* Aptr = A + (size_t)(bm + arow) * K + acol;
    const float* Bptr = Bm + (size_t)brow * N + bn + bcol;

    for (int k0 = 0; k0 < K; k0 += 8) {
        float4 av = *(const float4*)(Aptr + k0);
        float4 bv = *(const float4*)(Bptr + (size_t)k0 * N);
        __syncthreads();   // previous iteration's compute reads done
        As[acol + 0][arow] = av.x;
        As[acol + 1][arow] = av.y;
        As[acol + 2][arow] = av.z;
        As[acol + 3][arow] = av.w;
        *(float4*)(&Bs[brow][bcol]) = bv;
        __syncthreads();
#pragma unroll
        for (int k = 0; k < 8; k++) {
            float a[8], b[8];
            *(float4*)(&a[0]) = *(const float4*)(&As[k][tr * 8]);
            *(float4*)(&a[4]) = *(const float4*)(&As[k][tr * 8 + 4]);
            *(float4*)(&b[0]) = *(const float4*)(&Bs[k][tc * 8]);
            *(float4*)(&b[4]) = *(const float4*)(&Bs[k][tc * 8 + 4]);
#pragma unroll
            for (int i = 0; i < 8; i++)
#pragma unroll
                for (int j = 0; j < 8; j++)
                    acc[i][j] = fmaf(a[i], b[j], acc[i][j]);
        }
    }

#pragma unroll
    for (int i = 0; i < 8; i++) {
        float* crow = C + (size_t)(bm + tr * 8 + i) * N + bn + tc * 8;
        *(float4*)(crow)     = make_float4(acc[i][0], acc[i][1], acc[i][2], acc[i][3]);
        *(float4*)(crow + 4) = make_float4(acc[i][4], acc[i][5], acc[i][6], acc[i][7]);
    }
}

// ---------------------------------------------------------------------------
// Flash attention (causal), fp32. One CTA per (q_tile=64, head, batch).
// 256 threads = 16x16; each thread owns a 4x4 microtile of S and of O.
// Online softmax with 16-lane shuffle reductions.
// Smem: Q,K,V at row stride 64 (skewed column access -> conflict-free),
// P at row stride 68.
// ---------------------------------------------------------------------------
#define FA_SMEM_FLOATS (3 * 64 * 64 + 64 * 68)
#define FA_SMEM_BYTES  (FA_SMEM_FLOATS * 4)

__global__ __launch_bounds__(256) void flash_kernel(
    const float* __restrict__ qkv, float* __restrict__ out)
{
    extern __shared__ float sm[];
    float (*Qs)[64] = (float(*)[64])(sm);
    float (*Ks)[64] = (float(*)[64])(sm + 64 * 64);
    float (*Vs)[64] = (float(*)[64])(sm + 2 * 64 * 64);
    float (*Ps)[68] = (float(*)[68])(sm + 3 * 64 * 64);

    const int qt = blockIdx.x;     // 0..31
    const int h  = blockIdx.y;     // 0..15
    const int b  = blockIdx.z;     // 0..3
    const int q0 = qt * 64;

    const int tid = threadIdx.x;
    const int ty  = tid >> 4;      // 0..15
    const int tx  = tid & 15;      // 0..15

    const size_t base = (size_t)b * T_ * QKV_N;
    const float* qb = qkv + base + (size_t)h * HD_;
    const float* kb = qkv + base + D_ + (size_t)h * HD_;
    const float* vb = qkv + base + 2 * D_ + (size_t)h * HD_;

    // load Q tile [64 rows x 64 dims]
    {
        const int r = tid >> 2;
        const int c = (tid & 3) * 4;
#pragma unroll
        for (int j = 0; j < 4; j++)
            *(float4*)(&Qs[r][c + 16 * j]) =
                *(const float4*)(qb + (size_t)(q0 + r) * QKV_N + c + 16 * j);
    }

    float o[4][4];
    float m_i[4], l_i[4];
#pragma unroll
    for (int i = 0; i < 4; i++) {
        m_i[i] = -1e30f; l_i[i] = 0.0f;
#pragma unroll
        for (int j = 0; j < 4; j++) o[i][j] = 0.0f;
    }

    for (int kt = 0; kt <= qt; kt++) {
        const int k0 = kt * 64;
        __syncthreads();   // previous iter's smem reads complete
        {
            const int r = tid >> 2;
            const int c = (tid & 3) * 4;
#pragma unroll
            for (int j = 0; j < 4; j++) {
                *(float4*)(&Ks[r][c + 16 * j]) =
                    *(const float4*)(kb + (size_t)(k0 + r) * QKV_N + c + 16 * j);
                *(float4*)(&Vs[r][c + 16 * j]) =
                    *(const float4*)(vb + (size_t)(k0 + r) * QKV_N + c + 16 * j);
            }
        }
        __syncthreads();

        // S = Q @ K^T (64x64x64), tx-skewed d to avoid bank conflicts
        float s[4][4];
#pragma unroll
        for (int i = 0; i < 4; i++)
#pragma unroll
            for (int j = 0; j < 4; j++) s[i][j] = 0.0f;

#pragma unroll
        for (int d4 = 0; d4 < 16; d4++) {
            const int dd = ((d4 + tx) & 15) * 4;
            float4 q4[4], k4[4];
#pragma unroll
            for (int i = 0; i < 4; i++) q4[i] = *(const float4*)(&Qs[ty * 4 + i][dd]);
#pragma unroll
            for (int j = 0; j < 4; j++) k4[j] = *(const float4*)(&Ks[tx * 4 + j][dd]);
#pragma unroll
            for (int i = 0; i < 4; i++)
#pragma unroll
                for (int j = 0; j < 4; j++)
                    s[i][j] += q4[i].x * k4[j].x + q4[i].y * k4[j].y +
                               q4[i].z * k4[j].z + q4[i].w * k4[j].w;
        }

        const float scale = 0.125f;   // 1/sqrt(64)
        if (kt == qt) {
#pragma unroll
            for (int i = 0; i < 4; i++)
#pragma unroll
                for (int j = 0; j < 4; j++)
                    s[i][j] = (tx * 4 + j <= ty * 4 + i) ? s[i][j] * scale : -1e30f;
        } else {
#pragma unroll
            for (int i = 0; i < 4; i++)
#pragma unroll
                for (int j = 0; j < 4; j++) s[i][j] *= scale;
        }

        // online softmax per row (rows of one thread share ty -> reduce over tx)
#pragma unroll
        for (int i = 0; i < 4; i++) {
            float rm = fmaxf(fmaxf(s[i][0], s[i][1]), fmaxf(s[i][2], s[i][3]));
#pragma unroll
            for (int off = 1; off < 16; off <<= 1)
                rm = fmaxf(rm, __shfl_xor_sync(0xffffffffu, rm, off));
            const float mn = fmaxf(m_i[i], rm);
            const float alpha = __expf(m_i[i] - mn);
            float p0 = __expf(s[i][0] - mn);
            float p1 = __expf(s[i][1] - mn);
            float p2 = __expf(s[i][2] - mn);
            float p3 = __expf(s[i][3] - mn);
            float rs = p0 + p1 + p2 + p3;
#pragma unroll
            for (int off = 1; off < 16; off <<= 1)
                rs += __shfl_xor_sync(0xffffffffu, rs, off);
            l_i[i] = l_i[i] * alpha + rs;
            m_i[i] = mn;
#pragma unroll
            for (int j = 0; j < 4; j++) o[i][j] *= alpha;
            *(float4*)(&Ps[ty * 4 + i][tx * 4]) = make_float4(p0, p1, p2, p3);
        }
        __syncthreads();

        // O += P @ V (64x64x64), tx-skewed k to avoid bank conflicts
#pragma unroll
        for (int k4i = 0; k4i < 16; k4i++) {
            const int kk4 = (k4i + tx) & 15;
            float4 pr[4];
#pragma unroll
            for (int i = 0; i < 4; i++) pr[i] = *(const float4*)(&Ps[ty * 4 + i][kk4 * 4]);
            float4 vr[4];
#pragma unroll
            for (int kk = 0; kk < 4; kk++) vr[kk] = *(const float4*)(&Vs[kk4 * 4 + kk][tx * 4]);
#pragma unroll
            for (int i = 0; i < 4; i++) {
                o[i][0] += pr[i].x * vr[0].x + pr[i].y * vr[1].x + pr[i].z * vr[2].x + pr[i].w * vr[3].x;
                o[i][1] += pr[i].x * vr[0].y + pr[i].y * vr[1].y + pr[i].z * vr[2].y + pr[i].w * vr[3].y;
                o[i][2] += pr[i].x * vr[0].z + pr[i].y * vr[1].z + pr[i].z * vr[2].z + pr[i].w * vr[3].z;
                o[i][3] += pr[i].x * vr[0].w + pr[i].y * vr[1].w + pr[i].z * vr[2].w + pr[i].w * vr[3].w;
            }
        }
    }

    // finalize + write to [B,T, H*HD] layout (ready for the output projection)
#pragma unroll
    for (int i = 0; i < 4; i++) {
        const float inv = 1.0f / l_i[i];
        float4 v = make_float4(o[i][0] * inv, o[i][1] * inv, o[i][2] * inv, o[i][3] * inv);
        *(float4*)(out + (size_t)(b * T_ + q0 + ty * 4 + i) * D_ + h * HD_ + tx * 4) = v;
    }
}

// ---------------------------------------------------------------------------
// kernel_launch
// ---------------------------------------------------------------------------
extern "C" void kernel_launch(void* const* d_in, const int* in_sizes, int n_in,
                              void* d_out, int out_size)
{
    const float* x     = (const float*)d_in[0];   // [4,2048,1024]
    const float* w_qkv = (const float*)d_in[1];   // [1024,3072]
    const float* w_out = (const float*)d_in[2];   // [1024,1024]
    float* out = (float*)d_out;                   // [4,2048,1024]

    float* qkv = nullptr;
    float* att = nullptr;
    cudaGetSymbolAddress((void**)&qkv, g_qkv);
    cudaGetSymbolAddress((void**)&att, g_att);

    cudaFuncSetAttribute(flash_kernel,
                         cudaFuncAttributeMaxDynamicSharedMemorySize, FA_SMEM_BYTES);

    // 1) QKV projection: [8192,1024] @ [1024,3072]
    dim3 g1(QKV_N / 128, BT_ / 128);   // (24, 64)
    sgemm_kernel<<<g1, 256>>>(x, w_qkv, qkv, BT_, QKV_N, D_);

    // 2) causal flash attention
    dim3 g2(T_ / 64, H_, B_);          // (32, 16, 4)
    flash_kernel<<<g2, 256, FA_SMEM_BYTES>>>(qkv, att);

    // 3) output projection: [8192,1024] @ [1024,1024]
    dim3 g3(D_ / 128, BT_ / 128);      // (8, 64)
    sgemm_kernel<<<g3, 256>>>(att, w_out, out, BT_, D_, D_);
}

// round 4
// speedup vs baseline: 1.4583x; 1.4583x over previous
#include <cuda_runtime.h>
#include <cuda_bf16.h>
#include <cstdint>
#include <math.h>

#define B_  4
#define T_  2048
#define D_  1024
#define H_  16
#define HD_ 64
#define BT_ (B_ * T_)            // 8192
#define QKV_N (3 * D_)           // 3072

// ---------------------------------------------------------------------------
// Scratch (allocation-free rule: __device__ globals)
// ---------------------------------------------------------------------------
__device__ float g_qkv[(size_t)BT_ * QKV_N];        // fp32 q|k|v
__device__ float g_att[(size_t)BT_ * D_];           // fp32 attention out
__device__ __nv_bfloat16 g_xh[(size_t)BT_ * D_];    // x split hi
__device__ __nv_bfloat16 g_xl[(size_t)BT_ * D_];    // x split lo
__device__ __nv_bfloat16 g_ah[(size_t)BT_ * D_];    // att split hi
__device__ __nv_bfloat16 g_al[(size_t)BT_ * D_];    // att split lo
__device__ __nv_bfloat16 g_wqh[(size_t)QKV_N * D_]; // w_qkv^T hi  [N,K]
__device__ __nv_bfloat16 g_wql[(size_t)QKV_N * D_]; // w_qkv^T lo
__device__ __nv_bfloat16 g_woh[(size_t)D_ * D_];    // w_out^T hi
__device__ __nv_bfloat16 g_wol[(size_t)D_ * D_];    // w_out^T lo

// ---------------------------------------------------------------------------
// mma.sync helpers (sm_80-level PTX: valid at sm_103 base target)
// ---------------------------------------------------------------------------
__device__ __forceinline__ uint32_t smem_u32(const void* p) {
    uint32_t a;
    asm("{ .reg .u64 t; cvta.to.shared.u64 t, %1; cvt.u32.u64 %0, t; }"
        : "=r"(a) : "l"(p));
    return a;
}

__device__ __forceinline__ void ldmatrix_x4(uint32_t* r, uint32_t addr) {
    asm volatile("ldmatrix.sync.aligned.m8n8.x4.shared.b16 {%0,%1,%2,%3}, [%4];"
        : "=r"(r[0]), "=r"(r[1]), "=r"(r[2]), "=r"(r[3]) : "r"(addr));
}
__device__ __forceinline__ void ldmatrix_x2(uint32_t* r, uint32_t addr) {
    asm volatile("ldmatrix.sync.aligned.m8n8.x2.shared.b16 {%0,%1}, [%2];"
        : "=r"(r[0]), "=r"(r[1]) : "r"(addr));
}
__device__ __forceinline__ void mma_bf16(float* c, const uint32_t* a, const uint32_t* b) {
    asm volatile(
        "mma.sync.aligned.m16n8k16.row.col.f32.bf16.bf16.f32 "
        "{%0,%1,%2,%3}, {%4,%5,%6,%7}, {%8,%9}, {%0,%1,%2,%3};"
        : "+f"(c[0]), "+f"(c[1]), "+f"(c[2]), "+f"(c[3])
        : "r"(a[0]), "r"(a[1]), "r"(a[2]), "r"(a[3]), "r"(b[0]), "r"(b[1]));
}

// ---------------------------------------------------------------------------
// Split fp32 -> bf16 hi/lo (elementwise, vectorized x4)
// ---------------------------------------------------------------------------
__global__ __launch_bounds__(256) void convert_split_kernel(
    const float* __restrict__ in, __nv_bfloat16* __restrict__ hi,
    __nv_bfloat16* __restrict__ lo, int n4)
{
    int i = blockIdx.x * blockDim.x + threadIdx.x;
    if (i >= n4) return;
    float4 v = ((const float4*)in)[i];
    __nv_bfloat16 h0 = __float2bfloat16(v.x);
    __nv_bfloat16 h1 = __float2bfloat16(v.y);
    __nv_bfloat16 h2 = __float2bfloat16(v.z);
    __nv_bfloat16 h3 = __float2bfloat16(v.w);
    __nv_bfloat16 l0 = __float2bfloat16(v.x - __bfloat162float(h0));
    __nv_bfloat16 l1 = __float2bfloat16(v.y - __bfloat162float(h1));
    __nv_bfloat16 l2 = __float2bfloat16(v.z - __bfloat162float(h2));
    __nv_bfloat16 l3 = __float2bfloat16(v.w - __bfloat162float(h3));
    __nv_bfloat162* hp = (__nv_bfloat162*)hi;
    __nv_bfloat162* lp = (__nv_bfloat162*)lo;
    hp[2 * i]     = __halves2bfloat162(h0, h1);
    hp[2 * i + 1] = __halves2bfloat162(h2, h3);
    lp[2 * i]     = __halves2bfloat162(l0, l1);
    lp[2 * i + 1] = __halves2bfloat162(l2, l3);
}

// ---------------------------------------------------------------------------
// Transpose W[K,N] fp32 -> Bh/Bl[N,K] bf16 (hi/lo split)
// ---------------------------------------------------------------------------
__global__ __launch_bounds__(256) void transpose_split_kernel(
    const float* __restrict__ w, __nv_bfloat16* __restrict__ bh,
    __nv_bfloat16* __restrict__ bl, int K, int N)
{
    __shared__ float t[32][33];
    const int n0 = blockIdx.x * 32;
    const int k0 = blockIdx.y * 32;
    const int tx = threadIdx.x;
    const int ty = threadIdx.y;
#pragma unroll
    for (int i = 0; i < 32; i += 8)
        t[ty + i][tx] = w[(size_t)(k0 + ty + i) * N + n0 + tx];
    __syncthreads();
#pragma unroll
    for (int i = 0; i < 32; i += 8) {
        float v = t[tx][ty + i];   // = w[k0+tx][n0+ty+i]
        __nv_bfloat16 h = __float2bfloat16(v);
        __nv_bfloat16 l = __float2bfloat16(v - __bfloat162float(h));
        bh[(size_t)(n0 + ty + i) * K + k0 + tx] = h;
        bl[(size_t)(n0 + ty + i) * K + k0 + tx] = l;
    }
}

// ---------------------------------------------------------------------------
// HMMA GEMM: C[M,N] = (Ah+Al)[M,K] @ (Bh+Bl)[N,K]^T, fp32 accum.
// 128x128 CTA tile, BK=64, 256 threads (8 warps), warp = 64x32 via
// mma.sync m16n8k16. 3-term bf16 split: AhBh + AhBl + AlBh.
// Smem: padded stride 72 bf16 (conflict-free ldmatrix).
// ---------------------------------------------------------------------------
#define MBM 128
#define MBN 128
#define MBK 64
#define MSTRIDE 72                      // bf16 elements per smem row
#define MTILE_E (128 * MSTRIDE)         // elements per tile buffer
#define MSMEM_TOTAL (4 * MTILE_E * 2)   // Ah|Al|Bh|Bl bf16 = 73728 bytes

__device__ __forceinline__ void ld_tile_g2s(
    const __nv_bfloat16* __restrict__ src, int row0, int K, int k0,
    __nv_bfloat16* dst, int tid)
{
    // 128 rows x 64 bf16 = 1024 uint4; 256 threads x 4
#pragma unroll
    for (int i = 0; i < 4; i++) {
        int idx = tid + i * 256;
        int r   = idx >> 3;
        int c8  = idx & 7;
        uint4 v = *(const uint4*)(src + (size_t)(row0 + r) * K + k0 + c8 * 8);
        *(uint4*)(dst + r * MSTRIDE + c8 * 8) = v;
    }
}

__global__ __launch_bounds__(256) void hmma_gemm_kernel(
    const __nv_bfloat16* __restrict__ Ah, const __nv_bfloat16* __restrict__ Al,
    const __nv_bfloat16* __restrict__ Bh, const __nv_bfloat16* __restrict__ Bl,
    float* __restrict__ C, int M, int N, int K)
{
    extern __shared__ __nv_bfloat16 sm[];
    __nv_bfloat16* sAh = sm;
    __nv_bfloat16* sAl = sm + MTILE_E;
    __nv_bfloat16* sBh = sm + 2 * MTILE_E;
    __nv_bfloat16* sBl = sm + 3 * MTILE_E;

    const int tid = threadIdx.x;
    const int wid = tid >> 5;
    const int lid = tid & 31;
    const int bm  = blockIdx.y * MBM;
    const int bn  = blockIdx.x * MBN;
    const int wr  = wid >> 2;          // 0..1 -> m offset wr*64
    const int wc  = wid & 3;           // 0..3 -> n offset wc*32

    float c[4][4][4];
#pragma unroll
    for (int mi = 0; mi < 4; mi++)
#pragma unroll
        for (int ni = 0; ni < 4; ni++)
#pragma unroll
            for (int k = 0; k < 4; k++) c[mi][ni][k] = 0.0f;

    // ldmatrix source addresses (within-tile, element offsets)
    const int a_row = wr * 64 + (lid & 15);         // + mi*16
    const int a_col = (lid >> 4) * 8;               // + kk
    const int b_row = wc * 32 + (lid & 7);          // + ni*8
    const int b_col = ((lid >> 3) & 1) * 8;         // + kk

    const uint32_t sAh_u = smem_u32(sAh);
    const uint32_t sAl_u = smem_u32(sAl);
    const uint32_t sBh_u = smem_u32(sBh);
    const uint32_t sBl_u = smem_u32(sBl);
    const uint32_t a_off = (uint32_t)(a_row * MSTRIDE + a_col) * 2;
    const uint32_t b_off = (uint32_t)(b_row * MSTRIDE + b_col) * 2;

    for (int k0 = 0; k0 < K; k0 += MBK) {
        __syncthreads();
        ld_tile_g2s(Ah, bm, K, k0, sAh, tid);
        ld_tile_g2s(Al, bm, K, k0, sAl, tid);
        ld_tile_g2s(Bh, bn, K, k0, sBh, tid);
        ld_tile_g2s(Bl, bn, K, k0, sBl, tid);
        __syncthreads();

#pragma unroll
        for (int kk = 0; kk < MBK; kk += 16) {
            uint32_t af[4][4], bf[4][2];
            // Ah, Bh
#pragma unroll
            for (int mi = 0; mi < 4; mi++)
                ldmatrix_x4(af[mi], sAh_u + a_off + (uint32_t)(mi * 16 * MSTRIDE + kk) * 2);
#pragma unroll
            for (int ni = 0; ni < 4; ni++)
                ldmatrix_x2(bf[ni], sBh_u + b_off + (uint32_t)(ni * 8 * MSTRIDE + kk) * 2);
#pragma unroll
            for (int mi = 0; mi < 4; mi++)
#pragma unroll
                for (int ni = 0; ni < 4; ni++)
                    mma_bf16(c[mi][ni], af[mi], bf[ni]);
            // Ah, Bl
            uint32_t bl_[4][2];
#pragma unroll
            for (int ni = 0; ni < 4; ni++)
                ldmatrix_x2(bl_[ni], sBl_u + b_off + (uint32_t)(ni * 8 * MSTRIDE + kk) * 2);
#pragma unroll
            for (int mi = 0; mi < 4; mi++)
#pragma unroll
                for (int ni = 0; ni < 4; ni++)
                    mma_bf16(c[mi][ni], af[mi], bl_[ni]);
            // Al, Bh (reuse af regs)
#pragma unroll
            for (int mi = 0; mi < 4; mi++)
                ldmatrix_x4(af[mi], sAl_u + a_off + (uint32_t)(mi * 16 * MSTRIDE + kk) * 2);
#pragma unroll
            for (int mi = 0; mi < 4; mi++)
#pragma unroll
                for (int ni = 0; ni < 4; ni++)
                    mma_bf16(c[mi][ni], af[mi], bf[ni]);
        }
    }

    // epilogue: mma C layout -> global
    const int grp = lid >> 2;            // 0..7
    const int qd  = lid & 3;             // 0..3
#pragma unroll
    for (int mi = 0; mi < 4; mi++) {
        const int row_lo = bm + wr * 64 + mi * 16 + grp;
#pragma unroll
        for (int ni = 0; ni < 4; ni++) {
            const int col = bn + wc * 32 + ni * 8 + qd * 2;
            *(float2*)(C + (size_t)row_lo * N + col) =
                make_float2(c[mi][ni][0], c[mi][ni][1]);
            *(float2*)(C + (size_t)(row_lo + 8) * N + col) =
                make_float2(c[mi][ni][2], c[mi][ni][3]);
        }
    }
}

// ---------------------------------------------------------------------------
// Flash attention (causal), fp32 — unchanged from the passing R0 kernel.
// ---------------------------------------------------------------------------
#define FA_SMEM_FLOATS (3 * 64 * 64 + 64 * 68)
#define FA_SMEM_BYTES  (FA_SMEM_FLOATS * 4)

__global__ __launch_bounds__(256) void flash_kernel(
    const float* __restrict__ qkv, float* __restrict__ out)
{
    extern __shared__ float smf[];
    float (*Qs)[64] = (float(*)[64])(smf);
    float (*Ks)[64] = (float(*)[64])(smf + 64 * 64);
    float (*Vs)[64] = (float(*)[64])(smf + 2 * 64 * 64);
    float (*Ps)[68] = (float(*)[68])(smf + 3 * 64 * 64);

    const int qt = blockIdx.x;
    const int h  = blockIdx.y;
    const int b  = blockIdx.z;
    const int q0 = qt * 64;

    const int tid = threadIdx.x;
    const int ty  = tid >> 4;
    const int tx  = tid & 15;

    const size_t base = (size_t)b * T_ * QKV_N;
    const float* qb = qkv + base + (size_t)h * HD_;
    const float* kb = qkv + base + D_ + (size_t)h * HD_;
    const float* vb = qkv + base + 2 * D_ + (size_t)h * HD_;

    {
        const int r = tid >> 2;
        const int c = (tid & 3) * 4;
#pragma unroll
        for (int j = 0; j < 4; j++)
            *(float4*)(&Qs[r][c + 16 * j]) =
                *(const float4*)(qb + (size_t)(q0 + r) * QKV_N + c + 16 * j);
    }

    float o[4][4];
    float m_i[4], l_i[4];
#pragma unroll
    for (int i = 0; i < 4; i++) {
        m_i[i] = -1e30f; l_i[i] = 0.0f;
#pragma unroll
        for (int j = 0; j < 4; j++) o[i][j] = 0.0f;
    }

    for (int kt = 0; kt <= qt; kt++) {
        const int k0 = kt * 64;
        __syncthreads();
        {
            const int r = tid >> 2;
            const int c = (tid & 3) * 4;
#pragma unroll
            for (int j = 0; j < 4; j++) {
                *(float4*)(&Ks[r][c + 16 * j]) =
                    *(const float4*)(kb + (size_t)(k0 + r) * QKV_N + c + 16 * j);
                *(float4*)(&Vs[r][c + 16 * j]) =
                    *(const float4*)(vb + (size_t)(k0 + r) * QKV_N + c + 16 * j);
            }
        }
        __syncthreads();

        float s[4][4];
#pragma unroll
        for (int i = 0; i < 4; i++)
#pragma unroll
            for (int j = 0; j < 4; j++) s[i][j] = 0.0f;

#pragma unroll
        for (int d4 = 0; d4 < 16; d4++) {
            const int dd = ((d4 + tx) & 15) * 4;
            float4 q4[4], k4[4];
#pragma unroll
            for (int i = 0; i < 4; i++) q4[i] = *(const float4*)(&Qs[ty * 4 + i][dd]);
#pragma unroll
            for (int j = 0; j < 4; j++) k4[j] = *(const float4*)(&Ks[tx * 4 + j][dd]);
#pragma unroll
            for (int i = 0; i < 4; i++)
#pragma unroll
                for (int j = 0; j < 4; j++)
                    s[i][j] += q4[i].x * k4[j].x + q4[i].y * k4[j].y +
                               q4[i].z * k4[j].z + q4[i].w * k4[j].w;
        }

        const float scale = 0.125f;
        if (kt == qt) {
#pragma unroll
            for (int i = 0; i < 4; i++)
#pragma unroll
                for (int j = 0; j < 4; j++)
                    s[i][j] = (tx * 4 + j <= ty * 4 + i) ? s[i][j] * scale : -1e30f;
        } else {
#pragma unroll
            for (int i = 0; i < 4; i++)
#pragma unroll
                for (int j = 0; j < 4; j++) s[i][j] *= scale;
        }

#pragma unroll
        for (int i = 0; i < 4; i++) {
            float rm = fmaxf(fmaxf(s[i][0], s[i][1]), fmaxf(s[i][2], s[i][3]));
#pragma unroll
            for (int off = 1; off < 16; off <<= 1)
                rm = fmaxf(rm, __shfl_xor_sync(0xffffffffu, rm, off));
            const float mn = fmaxf(m_i[i], rm);
            const float alpha = __expf(m_i[i] - mn);
            float p0 = __expf(s[i][0] - mn);
            float p1 = __expf(s[i][1] - mn);
            float p2 = __expf(s[i][2] - mn);
            float p3 = __expf(s[i][3] - mn);
            float rs = p0 + p1 + p2 + p3;
#pragma unroll
            for (int off = 1; off < 16; off <<= 1)
                rs += __shfl_xor_sync(0xffffffffu, rs, off);
            l_i[i] = l_i[i] * alpha + rs;
            m_i[i] = mn;
#pragma unroll
            for (int j = 0; j < 4; j++) o[i][j] *= alpha;
            *(float4*)(&Ps[ty * 4 + i][tx * 4]) = make_float4(p0, p1, p2, p3);
        }
        __syncthreads();

#pragma unroll
        for (int k4i = 0; k4i < 16; k4i++) {
            const int kk4 = (k4i + tx) & 15;
            float4 pr[4];
#pragma unroll
            for (int i = 0; i < 4; i++) pr[i] = *(const float4*)(&Ps[ty * 4 + i][kk4 * 4]);
            float4 vr[4];
#pragma unroll
            for (int kk = 0; kk < 4; kk++) vr[kk] = *(const float4*)(&Vs[kk4 * 4 + kk][tx * 4]);
#pragma unroll
            for (int i = 0; i < 4; i++) {
                o[i][0] += pr[i].x * vr[0].x + pr[i].y * vr[1].x + pr[i].z * vr[2].x + pr[i].w * vr[3].x;
                o[i][1] += pr[i].x * vr[0].y + pr[i].y * vr[1].y + pr[i].z * vr[2].y + pr[i].w * vr[3].y;
                o[i][2] += pr[i].x * vr[0].z + pr[i].y * vr[1].z + pr[i].z * vr[2].z + pr[i].w * vr[3].z;
                o[i][3] += pr[i].x * vr[0].w + pr[i].y * vr[1].w + pr[i].z * vr[2].w + pr[i].w * vr[3].w;
            }
        }
    }

#pragma unroll
    for (int i = 0; i < 4; i++) {
        const float inv = 1.0f / l_i[i];
        float4 v = make_float4(o[i][0] * inv, o[i][1] * inv, o[i][2] * inv, o[i][3] * inv);
        *(float4*)(out + (size_t)(b * T_ + q0 + ty * 4 + i) * D_ + h * HD_ + tx * 4) = v;
    }
}

// ---------------------------------------------------------------------------
// kernel_launch
// ---------------------------------------------------------------------------
extern "C" void kernel_launch(void* const* d_in, const int* in_sizes, int n_in,
                              void* d_out, int out_size)
{
    const float* x     = (const float*)d_in[0];   // [4,2048,1024]
    const float* w_qkv = (const float*)d_in[1];   // [1024,3072]
    const float* w_out = (const float*)d_in[2];   // [1024,1024]
    float* out = (float*)d_out;                   // [4,2048,1024]

    float *qkv = nullptr, *att = nullptr;
    __nv_bfloat16 *xh, *xl, *ah, *al, *wqh, *wql, *woh, *wol;
    cudaGetSymbolAddress((void**)&qkv, g_qkv);
    cudaGetSymbolAddress((void**)&att, g_att);
    cudaGetSymbolAddress((void**)&xh,  g_xh);
    cudaGetSymbolAddress((void**)&xl,  g_xl);
    cudaGetSymbolAddress((void**)&ah,  g_ah);
    cudaGetSymbolAddress((void**)&al,  g_al);
    cudaGetSymbolAddress((void**)&wqh, g_wqh);
    cudaGetSymbolAddress((void**)&wql, g_wql);
    cudaGetSymbolAddress((void**)&woh, g_woh);
    cudaGetSymbolAddress((void**)&wol, g_wol);

    cudaFuncSetAttribute(flash_kernel,
                         cudaFuncAttributeMaxDynamicSharedMemorySize, FA_SMEM_BYTES);
    cudaFuncSetAttribute(hmma_gemm_kernel,
                         cudaFuncAttributeMaxDynamicSharedMemorySize, MSMEM_TOTAL);

    // split x -> bf16 hi/lo
    {
        int n4 = BT_ * D_ / 4;
        convert_split_kernel<<<(n4 + 255) / 256, 256>>>(x, xh, xl, n4);
    }
    // transpose+split weights: [K,N] -> [N,K]
    {
        dim3 b(32, 8);
        transpose_split_kernel<<<dim3(QKV_N / 32, D_ / 32), b>>>(w_qkv, wqh, wql, D_, QKV_N);
        transpose_split_kernel<<<dim3(D_ / 32,   D_ / 32), b>>>(w_out, woh, wol, D_, D_);
    }
    // 1) QKV projection (HMMA): [8192,1024] @ [1024,3072]
    {
        dim3 g(QKV_N / MBN, BT_ / MBM);   // (24, 64)
        hmma_gemm_kernel<<<g, 256, MSMEM_TOTAL>>>(xh, xl, wqh, wql, qkv, BT_, QKV_N, D_);
    }
    // 2) causal flash attention (fp32)
    {
        dim3 g(T_ / 64, H_, B_);
        flash_kernel<<<g, 256, FA_SMEM_BYTES>>>(qkv, att);
    }
    // split attention output
    {
        int n4 = BT_ * D_ / 4;
        convert_split_kernel<<<(n4 + 255) / 256, 256>>>(att, ah, al, n4);
    }
    // 3) output projection (HMMA): [8192,1024] @ [1024,1024]
    {
        dim3 g(D_ / MBN, BT_ / MBM);      // (8, 64)
        hmma_gemm_kernel<<<g, 256, MSMEM_TOTAL>>>(ah, al, woh, wol, out, BT_, D_, D_);
    }
}

// round 5
// speedup vs baseline: 2.8646x; 1.9643x over previous
#include <cuda_runtime.h>
#include <cuda_bf16.h>
#include <cstdint>
#include <math.h>

#define B_  4
#define T_  2048
#define D_  1024
#define H_  16
#define HD_ 64
#define BT_ (B_ * T_)            // 8192
#define QKV_N (3 * D_)           // 3072

// ---------------------------------------------------------------------------
// Scratch (allocation-free rule: __device__ globals)
// ---------------------------------------------------------------------------
__device__ float g_qkv[(size_t)BT_ * QKV_N];        // fp32 q|k|v
__device__ float g_att[(size_t)BT_ * D_];           // fp32 attention out
__device__ __nv_bfloat16 g_xh[(size_t)BT_ * D_];
__device__ __nv_bfloat16 g_xl[(size_t)BT_ * D_];
__device__ __nv_bfloat16 g_ah[(size_t)BT_ * D_];
__device__ __nv_bfloat16 g_al[(size_t)BT_ * D_];
__device__ __nv_bfloat16 g_wqh[(size_t)QKV_N * D_]; // w_qkv^T hi  [N,K]
__device__ __nv_bfloat16 g_wql[(size_t)QKV_N * D_];
__device__ __nv_bfloat16 g_woh[(size_t)D_ * D_];
__device__ __nv_bfloat16 g_wol[(size_t)D_ * D_];

// ---------------------------------------------------------------------------
// mma.sync / ldmatrix / cp.async helpers (sm_80-level PTX, valid at sm_103)
// ---------------------------------------------------------------------------
__device__ __forceinline__ uint32_t smem_u32(const void* p) {
    uint32_t a;
    asm("{ .reg .u64 t; cvta.to.shared.u64 t, %1; cvt.u32.u64 %0, t; }"
        : "=r"(a) : "l"(p));
    return a;
}
__device__ __forceinline__ void ldmatrix_x4(uint32_t* r, uint32_t addr) {
    asm volatile("ldmatrix.sync.aligned.m8n8.x4.shared.b16 {%0,%1,%2,%3}, [%4];"
        : "=r"(r[0]), "=r"(r[1]), "=r"(r[2]), "=r"(r[3]) : "r"(addr));
}
__device__ __forceinline__ void ldmatrix_x2(uint32_t* r, uint32_t addr) {
    asm volatile("ldmatrix.sync.aligned.m8n8.x2.shared.b16 {%0,%1}, [%2];"
        : "=r"(r[0]), "=r"(r[1]) : "r"(addr));
}
__device__ __forceinline__ void ldmatrix_x2_trans(uint32_t* r, uint32_t addr) {
    asm volatile("ldmatrix.sync.aligned.m8n8.x2.trans.shared.b16 {%0,%1}, [%2];"
        : "=r"(r[0]), "=r"(r[1]) : "r"(addr));
}
__device__ __forceinline__ void mma_bf16(float* c, const uint32_t* a, const uint32_t* b) {
    asm volatile(
        "mma.sync.aligned.m16n8k16.row.col.f32.bf16.bf16.f32 "
        "{%0,%1,%2,%3}, {%4,%5,%6,%7}, {%8,%9}, {%0,%1,%2,%3};"
        : "+f"(c[0]), "+f"(c[1]), "+f"(c[2]), "+f"(c[3])
        : "r"(a[0]), "r"(a[1]), "r"(a[2]), "r"(a[3]), "r"(b[0]), "r"(b[1]));
}
__device__ __forceinline__ void cp16(uint32_t dst, const void* src) {
    asm volatile("cp.async.cg.shared.global [%0], [%1], 16;" :: "r"(dst), "l"(src));
}
__device__ __forceinline__ void cp_commit() {
    asm volatile("cp.async.commit_group;" ::: "memory");
}
__device__ __forceinline__ void cp_wait1() {
    asm volatile("cp.async.wait_group 1;" ::: "memory");
}

// ---------------------------------------------------------------------------
// Split fp32 -> bf16 hi/lo
// ---------------------------------------------------------------------------
__global__ __launch_bounds__(256) void convert_split_kernel(
    const float* __restrict__ in, __nv_bfloat16* __restrict__ hi,
    __nv_bfloat16* __restrict__ lo, int n4)
{
    int i = blockIdx.x * blockDim.x + threadIdx.x;
    if (i >= n4) return;
    float4 v = ((const float4*)in)[i];
    __nv_bfloat16 h0 = __float2bfloat16(v.x);
    __nv_bfloat16 h1 = __float2bfloat16(v.y);
    __nv_bfloat16 h2 = __float2bfloat16(v.z);
    __nv_bfloat16 h3 = __float2bfloat16(v.w);
    __nv_bfloat16 l0 = __float2bfloat16(v.x - __bfloat162float(h0));
    __nv_bfloat16 l1 = __float2bfloat16(v.y - __bfloat162float(h1));
    __nv_bfloat16 l2 = __float2bfloat16(v.z - __bfloat162float(h2));
    __nv_bfloat16 l3 = __float2bfloat16(v.w - __bfloat162float(h3));
    __nv_bfloat162* hp = (__nv_bfloat162*)hi;
    __nv_bfloat162* lp = (__nv_bfloat162*)lo;
    hp[2 * i]     = __halves2bfloat162(h0, h1);
    hp[2 * i + 1] = __halves2bfloat162(h2, h3);
    lp[2 * i]     = __halves2bfloat162(l0, l1);
    lp[2 * i + 1] = __halves2bfloat162(l2, l3);
}

// ---------------------------------------------------------------------------
// Transpose W[K,N] fp32 -> Bh/Bl[N,K] bf16 (hi/lo split)
// ---------------------------------------------------------------------------
__global__ __launch_bounds__(256) void transpose_split_kernel(
    const float* __restrict__ w, __nv_bfloat16* __restrict__ bh,
    __nv_bfloat16* __restrict__ bl, int K, int N)
{
    __shared__ float t[32][33];
    const int n0 = blockIdx.x * 32;
    const int k0 = blockIdx.y * 32;
    const int tx = threadIdx.x;
    const int ty = threadIdx.y;
#pragma unroll
    for (int i = 0; i < 32; i += 8)
        t[ty + i][tx] = w[(size_t)(k0 + ty + i) * N + n0 + tx];
    __syncthreads();
#pragma unroll
    for (int i = 0; i < 32; i += 8) {
        float v = t[tx][ty + i];
        __nv_bfloat16 h = __float2bfloat16(v);
        __nv_bfloat16 l = __float2bfloat16(v - __bfloat162float(h));
        bh[(size_t)(n0 + ty + i) * K + k0 + tx] = h;
        bl[(size_t)(n0 + ty + i) * K + k0 + tx] = l;
    }
}

// ---------------------------------------------------------------------------
// HMMA GEMM with cp.async 2-stage pipeline.
// C[M,N] = (Ah+Al)[M,K] @ (Bh+Bl)[N,K]^T, fp32 accum, 3-term split.
// 128x128 CTA tile, BK=64, 8 warps, warp = 64x32 via m16n8k16.
// ---------------------------------------------------------------------------
#define MBM 128
#define MBN 128
#define MBK 64
#define MSTRIDE 72                       // bf16 elems per smem row (144B, 16B-mult)
#define MTILE_E (128 * MSTRIDE)          // elems per tile
#define MSTG_E  (4 * MTILE_E)            // Ah|Al|Bh|Bl per stage
#define MSMEM_TOTAL (2 * MSTG_E * 2)     // 2 stages, bytes = 147456

__global__ __launch_bounds__(256) void hmma_gemm_kernel(
    const __nv_bfloat16* __restrict__ Ah, const __nv_bfloat16* __restrict__ Al,
    const __nv_bfloat16* __restrict__ Bh, const __nv_bfloat16* __restrict__ Bl,
    float* __restrict__ C, int M, int N, int K)
{
    extern __shared__ __nv_bfloat16 sm[];
    const uint32_t sm_u = smem_u32(sm);

    const int tid = threadIdx.x;
    const int wid = tid >> 5;
    const int lid = tid & 31;
    const int bm  = blockIdx.y * MBM;
    const int bn  = blockIdx.x * MBN;
    const int wr  = wid >> 2;
    const int wc  = wid & 3;

    float c[4][4][4];
#pragma unroll
    for (int mi = 0; mi < 4; mi++)
#pragma unroll
        for (int ni = 0; ni < 4; ni++)
#pragma unroll
            for (int k = 0; k < 4; k++) c[mi][ni][k] = 0.0f;

    // cp.async per-thread mapping: 4 rows per tile (r0+32i), fixed 16B column
    const int r0  = tid >> 3;            // 0..31
    const int c16 = tid & 7;             // 0..7
    const uint32_t sm_off = (uint32_t)(r0 * 144 + c16 * 16);

    const __nv_bfloat16* gsrc[4] = {
        Ah + (size_t)(bm + r0) * K + c16 * 8,
        Al + (size_t)(bm + r0) * K + c16 * 8,
        Bh + (size_t)(bn + r0) * K + c16 * 8,
        Bl + (size_t)(bn + r0) * K + c16 * 8 };

    auto issue_chunk = [&](int ch, int stage) {
        const uint32_t sbase = sm_u + (uint32_t)stage * (MSTG_E * 2);
        const int k0 = ch * MBK;
#pragma unroll
        for (int t = 0; t < 4; t++) {
            const __nv_bfloat16* g = gsrc[t] + k0;
            const uint32_t sb = sbase + (uint32_t)t * (MTILE_E * 2) + sm_off;
#pragma unroll
            for (int i = 0; i < 4; i++)
                cp16(sb + (uint32_t)i * (32 * 144), g + (size_t)(32 * i) * K);
        }
    };

    // ldmatrix addresses (element offsets within a tile)
    const int a_row = wr * 64 + (lid & 15);
    const int a_col = (lid >> 4) * 8;
    const int b_row = wc * 32 + (lid & 7);
    const int b_col = ((lid >> 3) & 1) * 8;
    const uint32_t a_off = (uint32_t)(a_row * MSTRIDE + a_col) * 2;
    const uint32_t b_off = (uint32_t)(b_row * MSTRIDE + b_col) * 2;

    const int nch = K / MBK;
    issue_chunk(0, 0);
    cp_commit();

    for (int ch = 0; ch < nch; ch++) {
        const int s = ch & 1;
        if (ch + 1 < nch) issue_chunk(ch + 1, s ^ 1);
        cp_commit();
        cp_wait1();
        __syncthreads();

        const uint32_t st = sm_u + (uint32_t)s * (MSTG_E * 2);
        const uint32_t uAh = st;
        const uint32_t uAl = st + MTILE_E * 2;
        const uint32_t uBh = st + 2 * MTILE_E * 2;
        const uint32_t uBl = st + 3 * MTILE_E * 2;

#pragma unroll
        for (int kk = 0; kk < MBK; kk += 16) {
            uint32_t af[4][4], bf[4][2];
#pragma unroll
            for (int mi = 0; mi < 4; mi++)
                ldmatrix_x4(af[mi], uAh + a_off + (uint32_t)(mi * 16 * MSTRIDE + kk) * 2);
#pragma unroll
            for (int ni = 0; ni < 4; ni++)
                ldmatrix_x2(bf[ni], uBh + b_off + (uint32_t)(ni * 8 * MSTRIDE + kk) * 2);
#pragma unroll
            for (int mi = 0; mi < 4; mi++)
#pragma unroll
                for (int ni = 0; ni < 4; ni++)
                    mma_bf16(c[mi][ni], af[mi], bf[ni]);
            uint32_t bl_[4][2];
#pragma unroll
            for (int ni = 0; ni < 4; ni++)
                ldmatrix_x2(bl_[ni], uBl + b_off + (uint32_t)(ni * 8 * MSTRIDE + kk) * 2);
#pragma unroll
            for (int mi = 0; mi < 4; mi++)
#pragma unroll
                for (int ni = 0; ni < 4; ni++)
                    mma_bf16(c[mi][ni], af[mi], bl_[ni]);
#pragma unroll
            for (int mi = 0; mi < 4; mi++)
                ldmatrix_x4(af[mi], uAl + a_off + (uint32_t)(mi * 16 * MSTRIDE + kk) * 2);
#pragma unroll
            for (int mi = 0; mi < 4; mi++)
#pragma unroll
                for (int ni = 0; ni < 4; ni++)
                    mma_bf16(c[mi][ni], af[mi], bf[ni]);
        }
        __syncthreads();
    }

    const int grp = lid >> 2;
    const int qd  = lid & 3;
#pragma unroll
    for (int mi = 0; mi < 4; mi++) {
        const int row_lo = bm + wr * 64 + mi * 16 + grp;
#pragma unroll
        for (int ni = 0; ni < 4; ni++) {
            const int col = bn + wc * 32 + ni * 8 + qd * 2;
            *(float2*)(C + (size_t)row_lo * N + col) =
                make_float2(c[mi][ni][0], c[mi][ni][1]);
            *(float2*)(C + (size_t)(row_lo + 8) * N + col) =
                make_float2(c[mi][ni][2], c[mi][ni][3]);
        }
    }
}

// ---------------------------------------------------------------------------
// HMMA flash attention (causal). BM=128 q rows/CTA, BN=64 keys/iter, HD=64.
// 8 warps x 16 q-rows. 3-term bf16 splits for QK^T and PV. fp32 softmax in
// mma fragments (no P smem). V fragments via ldmatrix.trans.
// ---------------------------------------------------------------------------
#define FSTR 72
#define FQH 0
#define FQL (128 * FSTR)
#define FKH (256 * FSTR)
#define FKL (320 * FSTR)
#define FVH (384 * FSTR)
#define FVL (448 * FSTR)
#define F_SMEM_E (512 * FSTR)
#define F_SMEM_BYTES (F_SMEM_E * 2)      // 73728

__global__ __launch_bounds__(256, 2) void flash_hmma_kernel(
    const float* __restrict__ qkv, float* __restrict__ out)
{
    extern __shared__ __nv_bfloat16 fsm[];
    const uint32_t sm_u = smem_u32(fsm);

    const int qtile = blockIdx.x;        // 0..15
    const int h  = blockIdx.y;
    const int b  = blockIdx.z;
    const int q0 = qtile * 128;

    const int tid = threadIdx.x;
    const int wid = tid >> 5;
    const int lid = tid & 31;
    const int grp = lid >> 2;
    const int qd  = lid & 3;
    const int w16 = wid * 16;

    const size_t base = (size_t)b * T_ * QKV_N;
    const float* qb = qkv + base + (size_t)h * HD_;
    const float* kb = qkv + base + D_ + (size_t)h * HD_;
    const float* vb = qkv + base + 2 * D_ + (size_t)h * HD_;

    // ---- load Q tile (128x64) -> hi/lo bf16 smem ----
    {
        const int r = tid >> 1;
        const int cb = (tid & 1) * 32;
        const float* src = qb + (size_t)(q0 + r) * QKV_N + cb;
        __nv_bfloat16* dh = fsm + FQH + r * FSTR + cb;
        __nv_bfloat16* dl = fsm + FQL + r * FSTR + cb;
#pragma unroll
        for (int j = 0; j < 8; j++) {
            float4 v = *(const float4*)(src + j * 4);
            __nv_bfloat16 h0 = __float2bfloat16(v.x), h1 = __float2bfloat16(v.y);
            __nv_bfloat16 h2 = __float2bfloat16(v.z), h3 = __float2bfloat16(v.w);
            ((__nv_bfloat162*)(dh + j * 4))[0] = __halves2bfloat162(h0, h1);
            ((__nv_bfloat162*)(dh + j * 4))[1] = __halves2bfloat162(h2, h3);
            ((__nv_bfloat162*)(dl + j * 4))[0] = __halves2bfloat162(
                __float2bfloat16(v.x - __bfloat162float(h0)),
                __float2bfloat16(v.y - __bfloat162float(h1)));
            ((__nv_bfloat162*)(dl + j * 4))[1] = __halves2bfloat162(
                __float2bfloat16(v.z - __bfloat162float(h2)),
                __float2bfloat16(v.w - __bfloat162float(h3)));
        }
    }

    float o[8][4];
#pragma unroll
    for (int ni = 0; ni < 8; ni++)
#pragma unroll
        for (int k = 0; k < 4; k++) o[ni][k] = 0.0f;
    float m0 = -1e30f, m1 = -1e30f, l0 = 0.0f, l1 = 0.0f;

    // ldmatrix element->byte offsets
    const uint32_t a_off = (uint32_t)((w16 + (lid & 15)) * FSTR + (lid >> 4) * 8) * 2;
    const uint32_t b_off = (uint32_t)(((lid & 7)) * FSTR + ((lid >> 3) & 1) * 8) * 2;
    const uint32_t v_off = (uint32_t)((lid & 15) * FSTR) * 2;

    const uint32_t uQH = sm_u + FQH * 2, uQL = sm_u + FQL * 2;
    const uint32_t uKH = sm_u + FKH * 2, uKL = sm_u + FKL * 2;
    const uint32_t uVH = sm_u + FVH * 2, uVL = sm_u + FVL * 2;

    const int row0_abs = q0 + w16 + grp;

    auto tile = [&](int kt, bool masked) {
        const int k0 = kt * 64;
        __syncthreads();   // prev iter's smem reads done
        {
            const int r = tid >> 2;
            const int cb = (tid & 3) * 16;
            const float* ks = kb + (size_t)(k0 + r) * QKV_N + cb;
            const float* vs = vb + (size_t)(k0 + r) * QKV_N + cb;
            __nv_bfloat16* kh = fsm + FKH + r * FSTR + cb;
            __nv_bfloat16* kl = fsm + FKL + r * FSTR + cb;
            __nv_bfloat16* vh = fsm + FVH + r * FSTR + cb;
            __nv_bfloat16* vl = fsm + FVL + r * FSTR + cb;
#pragma unroll
            for (int j = 0; j < 4; j++) {
                float4 kv = *(const float4*)(ks + j * 4);
                float4 vv = *(const float4*)(vs + j * 4);
                __nv_bfloat16 a0 = __float2bfloat16(kv.x), a1 = __float2bfloat16(kv.y);
                __nv_bfloat16 a2 = __float2bfloat16(kv.z), a3 = __float2bfloat16(kv.w);
                ((__nv_bfloat162*)(kh + j * 4))[0] = __halves2bfloat162(a0, a1);
                ((__nv_bfloat162*)(kh + j * 4))[1] = __halves2bfloat162(a2, a3);
                ((__nv_bfloat162*)(kl + j * 4))[0] = __halves2bfloat162(
                    __float2bfloat16(kv.x - __bfloat162float(a0)),
                    __float2bfloat16(kv.y - __bfloat162float(a1)));
                ((__nv_bfloat162*)(kl + j * 4))[1] = __halves2bfloat162(
                    __float2bfloat16(kv.z - __bfloat162float(a2)),
                    __float2bfloat16(kv.w - __bfloat162float(a3)));
                __nv_bfloat16 b0 = __float2bfloat16(vv.x), b1 = __float2bfloat16(vv.y);
                __nv_bfloat16 b2 = __float2bfloat16(vv.z), b3 = __float2bfloat16(vv.w);
                ((__nv_bfloat162*)(vh + j * 4))[0] = __halves2bfloat162(b0, b1);
                ((__nv_bfloat162*)(vh + j * 4))[1] = __halves2bfloat162(b2, b3);
                ((__nv_bfloat162*)(vl + j * 4))[0] = __halves2bfloat162(
                    __float2bfloat16(vv.x - __bfloat162float(b0)),
                    __float2bfloat16(vv.y - __bfloat162float(b1)));
                ((__nv_bfloat162*)(vl + j * 4))[1] = __halves2bfloat162(
                    __float2bfloat16(vv.z - __bfloat162float(b2)),
                    __float2bfloat16(vv.w - __bfloat162float(b3)));
            }
        }
        __syncthreads();

        // ---- S = Q K^T (3-term split) ----
        float s[8][4];
#pragma unroll
        for (int ni = 0; ni < 8; ni++)
#pragma unroll
            for (int k = 0; k < 4; k++) s[ni][k] = 0.0f;

#pragma unroll
        for (int kk4 = 0; kk4 < 4; kk4++) {
            const uint32_t ko = (uint32_t)kk4 * 32;   // 16 elems * 2B
            uint32_t qh[4], ql[4];
            ldmatrix_x4(qh, uQH + a_off + ko);
            ldmatrix_x4(ql, uQL + a_off + ko);
#pragma unroll
            for (int ni = 0; ni < 8; ni++) {
                const uint32_t no = (uint32_t)(ni * 8 * FSTR) * 2;
                uint32_t kh[2], kl[2];
                ldmatrix_x2(kh, uKH + b_off + no + ko);
                ldmatrix_x2(kl, uKL + b_off + no + ko);
                mma_bf16(s[ni], qh, kh);
                mma_bf16(s[ni], qh, kl);
                mma_bf16(s[ni], ql, kh);
            }
        }

        // ---- scale + mask ----
        const float scale = 0.125f;
#pragma unroll
        for (int ni = 0; ni < 8; ni++) {
#pragma unroll
            for (int k = 0; k < 4; k++) s[ni][k] *= scale;
            if (masked) {
                const int col = k0 + ni * 8 + qd * 2;
                if (col > row0_abs)     s[ni][0] = -1e30f;
                if (col + 1 > row0_abs) s[ni][1] = -1e30f;
                if (col > row0_abs + 8)     s[ni][2] = -1e30f;
                if (col + 1 > row0_abs + 8) s[ni][3] = -1e30f;
            }
        }

        // ---- online softmax (rows grp, grp+8; quad = same row) ----
        float mx0 = -1e30f, mx1 = -1e30f;
#pragma unroll
        for (int ni = 0; ni < 8; ni++) {
            mx0 = fmaxf(mx0, fmaxf(s[ni][0], s[ni][1]));
            mx1 = fmaxf(mx1, fmaxf(s[ni][2], s[ni][3]));
        }
        mx0 = fmaxf(mx0, __shfl_xor_sync(0xffffffffu, mx0, 1));
        mx0 = fmaxf(mx0, __shfl_xor_sync(0xffffffffu, mx0, 2));
        mx1 = fmaxf(mx1, __shfl_xor_sync(0xffffffffu, mx1, 1));
        mx1 = fmaxf(mx1, __shfl_xor_sync(0xffffffffu, mx1, 2));
        const float mn0 = fmaxf(m0, mx0);
        const float mn1 = fmaxf(m1, mx1);
        const float al0 = __expf(m0 - mn0);
        const float al1 = __expf(m1 - mn1);

        uint32_t pH[8][2], pL[8][2];
        float sum0 = 0.0f, sum1 = 0.0f;
#pragma unroll
        for (int ni = 0; ni < 8; ni++) {
            float p0 = __expf(s[ni][0] - mn0);
            float p1 = __expf(s[ni][1] - mn0);
            float p2 = __expf(s[ni][2] - mn1);
            float p3 = __expf(s[ni][3] - mn1);
            sum0 += p0 + p1; sum1 += p2 + p3;
            __nv_bfloat16 h0 = __float2bfloat16(p0), h1 = __float2bfloat16(p1);
            __nv_bfloat16 h2 = __float2bfloat16(p2), h3 = __float2bfloat16(p3);
            __nv_bfloat162 ph01 = __halves2bfloat162(h0, h1);
            __nv_bfloat162 ph23 = __halves2bfloat162(h2, h3);
            __nv_bfloat162 pl01 = __halves2bfloat162(
                __float2bfloat16(p0 - __bfloat162float(h0)),
                __float2bfloat16(p1 - __bfloat162float(h1)));
            __nv_bfloat162 pl23 = __halves2bfloat162(
                __float2bfloat16(p2 - __bfloat162float(h2)),
                __float2bfloat16(p3 - __bfloat162float(h3)));
            pH[ni][0] = *(uint32_t*)&ph01; pH[ni][1] = *(uint32_t*)&ph23;
            pL[ni][0] = *(uint32_t*)&pl01; pL[ni][1] = *(uint32_t*)&pl23;
        }
        sum0 += __shfl_xor_sync(0xffffffffu, sum0, 1);
        sum0 += __shfl_xor_sync(0xffffffffu, sum0, 2);
        sum1 += __shfl_xor_sync(0xffffffffu, sum1, 1);
        sum1 += __shfl_xor_sync(0xffffffffu, sum1, 2);
        l0 = l0 * al0 + sum0;
        l1 = l1 * al1 + sum1;
        m0 = mn0; m1 = mn1;
#pragma unroll
        for (int ni = 0; ni < 8; ni++) {
            o[ni][0] *= al0; o[ni][1] *= al0;
            o[ni][2] *= al1; o[ni][3] *= al1;
        }

        // ---- O += P V (3-term split); V frags via ldmatrix.trans ----
#pragma unroll
        for (int j = 0; j < 4; j++) {
            uint32_t ah[4] = { pH[2 * j][0], pH[2 * j][1], pH[2 * j + 1][0], pH[2 * j + 1][1] };
            uint32_t al_[4] = { pL[2 * j][0], pL[2 * j][1], pL[2 * j + 1][0], pL[2 * j + 1][1] };
            const uint32_t jo = (uint32_t)(j * 16 * FSTR) * 2;
#pragma unroll
            for (int ni = 0; ni < 8; ni++) {
                const uint32_t no = (uint32_t)(ni * 8) * 2;
                uint32_t vh[2], vl[2];
                ldmatrix_x2_trans(vh, uVH + v_off + jo + no);
                ldmatrix_x2_trans(vl, uVL + v_off + jo + no);
                mma_bf16(o[ni], ah, vh);
                mma_bf16(o[ni], al_, vh);
                mma_bf16(o[ni], ah, vl);
            }
        }
    };

    for (int kt = 0; kt < 2 * qtile; kt++) tile(kt, false);
    tile(2 * qtile, true);
    tile(2 * qtile + 1, true);

    // ---- finalize, write [B,T,H*HD] fp32 ----
    const float inv0 = 1.0f / l0;
    const float inv1 = 1.0f / l1;
    float* orow0 = out + (size_t)(b * T_ + row0_abs) * D_ + h * HD_;
    float* orow1 = orow0 + (size_t)8 * D_;
#pragma unroll
    for (int ni = 0; ni < 8; ni++) {
        *(float2*)(orow0 + ni * 8 + qd * 2) = make_float2(o[ni][0] * inv0, o[ni][1] * inv0);
        *(float2*)(orow1 + ni * 8 + qd * 2) = make_float2(o[ni][2] * inv1, o[ni][3] * inv1);
    }
}

// ---------------------------------------------------------------------------
// kernel_launch
// ---------------------------------------------------------------------------
extern "C" void kernel_launch(void* const* d_in, const int* in_sizes, int n_in,
                              void* d_out, int out_size)
{
    const float* x     = (const float*)d_in[0];
    const float* w_qkv = (const float*)d_in[1];
    const float* w_out = (const float*)d_in[2];
    float* out = (float*)d_out;

    float *qkv = nullptr, *att = nullptr;
    __nv_bfloat16 *xh, *xl, *ah, *al, *wqh, *wql, *woh, *wol;
    cudaGetSymbolAddress((void**)&qkv, g_qkv);
    cudaGetSymbolAddress((void**)&att, g_att);
    cudaGetSymbolAddress((void**)&xh,  g_xh);
    cudaGetSymbolAddress((void**)&xl,  g_xl);
    cudaGetSymbolAddress((void**)&ah,  g_ah);
    cudaGetSymbolAddress((void**)&al,  g_al);
    cudaGetSymbolAddress((void**)&wqh, g_wqh);
    cudaGetSymbolAddress((void**)&wql, g_wql);
    cudaGetSymbolAddress((void**)&woh, g_woh);
    cudaGetSymbolAddress((void**)&wol, g_wol);

    cudaFuncSetAttribute(hmma_gemm_kernel,
                         cudaFuncAttributeMaxDynamicSharedMemorySize, MSMEM_TOTAL);
    cudaFuncSetAttribute(flash_hmma_kernel,
                         cudaFuncAttributeMaxDynamicSharedMemorySize, F_SMEM_BYTES);

    {
        int n4 = BT_ * D_ / 4;
        convert_split_kernel<<<(n4 + 255) / 256, 256>>>(x, xh, xl, n4);
    }
    {
        dim3 bb(32, 8);
        transpose_split_kernel<<<dim3(QKV_N / 32, D_ / 32), bb>>>(w_qkv, wqh, wql, D_, QKV_N);
        transpose_split_kernel<<<dim3(D_ / 32,   D_ / 32), bb>>>(w_out, woh, wol, D_, D_);
    }
    {
        dim3 g(QKV_N / MBN, BT_ / MBM);
        hmma_gemm_kernel<<<g, 256, MSMEM_TOTAL>>>(xh, xl, wqh, wql, qkv, BT_, QKV_N, D_);
    }
    {
        dim3 g(T_ / 128, H_, B_);   // (16,16,4)
        flash_hmma_kernel<<<g, 256, F_SMEM_BYTES>>>(qkv, att);
    }
    {
        int n4 = BT_ * D_ / 4;
        convert_split_kernel<<<(n4 + 255) / 256, 256>>>(att, ah, al, n4);
    }
    {
        dim3 g(D_ / MBN, BT_ / MBM);
        hmma_gemm_kernel<<<g, 256, MSMEM_TOTAL>>>(ah, al, woh, wol, out, BT_, D_, D_);
    }
}